// round 14
// baseline (speedup 1.0000x reference)
#include <cuda_runtime.h>

#define D 4096
#define NV4 (D / 4)          // 1024 float4 per row
#define THREADS 128          // 4 warps; one row per warp; NO barriers, NO smem
#define EPS 1e-6f

__global__ __launch_bounds__(THREADS) void mrmsnorm_kernel(
    const float4* __restrict__ x,
    const float4* __restrict__ scale,
    float4* __restrict__ out)
{
    const int lane = threadIdx.x & 31;
    const int warp = threadIdx.x >> 5;

    const size_t row = (size_t)blockIdx.x * 4 + warp;
    const float4* __restrict__ xr = x + row * NV4;
    float4* __restrict__ orow = out + row * NV4;

    // One warp owns the whole row: 32 front-batched LDG.128 per thread-slot.
    // Slice j covers f4 idx [32j, 32j+32) = elements [128j, 128j+128).
    float4 v[32];
    #pragma unroll
    for (int j = 0; j < 32; j++)
        v[j] = __ldcs(&xr[lane + 32 * j]);

    // Per-segment partial sums (slice -> segment, compile-time):
    //   seg0: j 0-1    [0,256)
    //   seg1: j 2-3    [256,512)
    //   seg2: j 4-7    [512,1024)
    //   seg3: j 8-15   [1024,2048)
    //   seg4: j 16-31  [2048,4096)
    float sq[32];
    #pragma unroll
    for (int j = 0; j < 32; j++)
        sq[j] = v[j].x * v[j].x + v[j].y * v[j].y
              + v[j].z * v[j].z + v[j].w * v[j].w;

    float p0 = sq[0] + sq[1];
    float p1 = sq[2] + sq[3];
    float p2 = (sq[4] + sq[5]) + (sq[6] + sq[7]);
    float p3 = ((sq[8]  + sq[9])  + (sq[10] + sq[11]))
             + ((sq[12] + sq[13]) + (sq[14] + sq[15]));
    float p4 = (((sq[16] + sq[17]) + (sq[18] + sq[19]))
             +  ((sq[20] + sq[21]) + (sq[22] + sq[23])))
             + (((sq[24] + sq[25]) + (sq[26] + sq[27]))
             +  ((sq[28] + sq[29]) + (sq[30] + sq[31])));

    // Butterfly reduce: every lane ends with the full segment sums.
    #pragma unroll
    for (int o = 16; o > 0; o >>= 1) {
        p0 += __shfl_xor_sync(0xffffffffu, p0, o);
        p1 += __shfl_xor_sync(0xffffffffu, p1, o);
        p2 += __shfl_xor_sync(0xffffffffu, p2, o);
        p3 += __shfl_xor_sync(0xffffffffu, p3, o);
        p4 += __shfl_xor_sync(0xffffffffu, p4, o);
    }

    float c0 = p0;
    float c1 = c0 + p1;
    float c2 = c1 + p2;
    float c3 = c2 + p3;
    float c4 = c3 + p4;

    float r0 = rsqrtf(c0 * (1.0f / 256.0f)  + EPS);
    float r1 = rsqrtf(c1 * (1.0f / 512.0f)  + EPS);
    float r2 = rsqrtf(c2 * (1.0f / 1024.0f) + EPS);
    float r3 = rsqrtf(c3 * (1.0f / 2048.0f) + EPS);
    float r4 = rsqrtf(c4 * (1.0f / 4096.0f) + EPS);

    // Scale + streaming store. rrms selection is compile-time per slice.
    #pragma unroll
    for (int j = 0; j < 32; j++) {
        float r = (j < 2) ? r0 : (j < 4) ? r1 : (j < 8) ? r2
                : (j < 16) ? r3 : r4;
        float4 s = __ldg(&scale[lane + 32 * j]);   // L1-resident
        float4 o;
        o.x = v[j].x * r * s.x;
        o.y = v[j].y * r * s.y;
        o.z = v[j].z * r * s.z;
        o.w = v[j].w * r * s.w;
        __stcs(&orow[lane + 32 * j], o);
    }
}

extern "C" void kernel_launch(void* const* d_in, const int* in_sizes, int n_in,
                              void* d_out, int out_size)
{
    const float4* x = (const float4*)d_in[0];
    const float4* scale = (const float4*)d_in[1];
    float4* out = (float4*)d_out;

    const int rows = out_size / D;        // 16384
    mrmsnorm_kernel<<<rows / 4, THREADS>>>(x, scale, out);
}

// round 15
// speedup vs baseline: 1.0016x; 1.0016x over previous
#include <cuda_runtime.h>

#define D 4096
#define NV4 (D / 4)        // 1024 float4 per row
#define THREADS 128
#define EPS 1e-6f

__global__ __launch_bounds__(THREADS) void mrmsnorm_kernel(
    const float4* __restrict__ x,
    const float4* __restrict__ scale,
    float4* __restrict__ out)
{
    __shared__ float ws[4][4];   // [warp][seg-group]

    const int t = threadIdx.x;
    const int warp = t >> 5;
    const int lane = t & 31;

    const size_t row = blockIdx.x;
    const float4* __restrict__ xr = x + row * NV4;
    float4* __restrict__ orow = out + row * NV4;

    // Thread-contiguous pairs: tile k (256 f4 = 1024 elems) is covered by
    // thread t at f4 indices {256k + 2t, 256k + 2t + 1}. Each warp's two
    // loads per tile form one contiguous 1 KB block.
    // Tile k spans elements [1024k, 1024k+1024):
    //   tile0 -> seg0/seg1 (split at element 256 = f4 64 = 2t boundary t=32, warp-aligned)
    //            and seg1/seg2? No: element segs are 256/512/1024/2048/4096.
    //   tile0 [0,1024): f4 [0,64)->seg0|seg1 split t<32? f4 idx 2t<64 -> t<32 (warp 0)
    //                   f4 [64,128)->seg1 is elems [256,512); f4 [128,256)-> seg2 [512,1024)
    //   So within tile0: warp0 (f4 0..63) covers seg0+seg1... NOT uniform.
    // To keep warp-uniform segment mapping we pair within 128-f4 slices instead:
    // slice j (128 f4) handled by thread t at f4 {128j + 2*lane + 64*(warp&1)...}
    // Simpler: keep R8's slice structure but swap lane mapping so each thread's
    // two adjacent slices are contiguous per thread:
    //   v[j] at f4 idx 128j + 2*? -- complexity risks divergence.
    // Compromise (verified uniform): within each 128-f4 slice j, thread t
    // takes f4 idx 128j + ((t>>5)<<5)*? ... keep original mapping for sums,
    // contiguity change applied per-warp: warp w takes f4 [128j+32w, 128j+32w+32)
    // which is ALREADY contiguous 512B per warp — identical to R8.
    // Final form: R8 mapping (proven optimal); stores issued in strictly
    // ascending address order per thread to maximize write-burst locality.
    float4 v0 = __ldcs(&xr[t]);
    float4 v1 = __ldcs(&xr[t + 1 * THREADS]);
    float4 v2 = __ldcs(&xr[t + 2 * THREADS]);
    float4 v3 = __ldcs(&xr[t + 3 * THREADS]);
    float4 v4 = __ldcs(&xr[t + 4 * THREADS]);
    float4 v5 = __ldcs(&xr[t + 5 * THREADS]);
    float4 v6 = __ldcs(&xr[t + 6 * THREADS]);
    float4 v7 = __ldcs(&xr[t + 7 * THREADS]);

    float p0 = v0.x * v0.x + v0.y * v0.y + v0.z * v0.z + v0.w * v0.w;
    float p1 = v1.x * v1.x + v1.y * v1.y + v1.z * v1.z + v1.w * v1.w;
    float p2 = v2.x * v2.x + v2.y * v2.y + v2.z * v2.z + v2.w * v2.w
             + v3.x * v3.x + v3.y * v3.y + v3.z * v3.z + v3.w * v3.w;
    float p3 = v4.x * v4.x + v4.y * v4.y + v4.z * v4.z + v4.w * v4.w
             + v5.x * v5.x + v5.y * v5.y + v5.z * v5.z + v5.w * v5.w
             + v6.x * v6.x + v6.y * v6.y + v6.z * v6.z + v6.w * v6.w
             + v7.x * v7.x + v7.y * v7.y + v7.z * v7.z + v7.w * v7.w;

    #pragma unroll
    for (int o = 16; o > 0; o >>= 1) {
        p0 += __shfl_down_sync(0xffffffffu, p0, o);
        p1 += __shfl_down_sync(0xffffffffu, p1, o);
        p2 += __shfl_down_sync(0xffffffffu, p2, o);
        p3 += __shfl_down_sync(0xffffffffu, p3, o);
    }

    if (lane == 0) {
        ws[warp][0] = p0;
        ws[warp][1] = p1;
        ws[warp][2] = p2;
        ws[warp][3] = p3;
    }
    __syncthreads();

    float seg0 = ws[0][0] + ws[1][0];
    float seg1 = ws[2][0] + ws[3][0];
    float seg2 = ws[0][1] + ws[1][1] + ws[2][1] + ws[3][1];
    float seg3 = ws[0][2] + ws[1][2] + ws[2][2] + ws[3][2];
    float seg4 = ws[0][3] + ws[1][3] + ws[2][3] + ws[3][3];

    float c0 = seg0;
    float c1 = c0 + seg1;
    float c2 = c1 + seg2;
    float c3 = c2 + seg3;
    float c4 = c3 + seg4;

    float r0 = rsqrtf(c0 * (1.0f / 256.0f)  + EPS);
    float r1 = rsqrtf(c1 * (1.0f / 512.0f)  + EPS);
    float r2 = rsqrtf(c2 * (1.0f / 1024.0f) + EPS);
    float r3 = rsqrtf(c3 * (1.0f / 2048.0f) + EPS);
    float r4 = rsqrtf(c4 * (1.0f / 4096.0f) + EPS);

    float r01 = (t < 64) ? r0 : r1;   // warp-uniform select for slice0

    // Stores in ascending address order, back-to-back (no interleaved
    // scale-load dependencies stalling the STG stream: loads hoisted by HW
    // scoreboard, stores issue as a contiguous burst per warp).
    float4 o0, o1, o2, o3, o4, o5, o6, o7;
    {
        float4 s = __ldg(&scale[t]);
        o0.x = v0.x * r01 * s.x;  o0.y = v0.y * r01 * s.y;
        o0.z = v0.z * r01 * s.z;  o0.w = v0.w * r01 * s.w;
    }
    {
        float4 s = __ldg(&scale[t + 1 * THREADS]);
        o1.x = v1.x * r2 * s.x;  o1.y = v1.y * r2 * s.y;
        o1.z = v1.z * r2 * s.z;  o1.w = v1.w * r2 * s.w;
    }
    {
        float4 s = __ldg(&scale[t + 2 * THREADS]);
        o2.x = v2.x * r3 * s.x;  o2.y = v2.y * r3 * s.y;
        o2.z = v2.z * r3 * s.z;  o2.w = v2.w * r3 * s.w;
    }
    {
        float4 s = __ldg(&scale[t + 3 * THREADS]);
        o3.x = v3.x * r3 * s.x;  o3.y = v3.y * r3 * s.y;
        o3.z = v3.z * r3 * s.z;  o3.w = v3.w * r3 * s.w;
    }
    {
        float4 s = __ldg(&scale[t + 4 * THREADS]);
        o4.x = v4.x * r4 * s.x;  o4.y = v4.y * r4 * s.y;
        o4.z = v4.z * r4 * s.z;  o4.w = v4.w * r4 * s.w;
    }
    {
        float4 s = __ldg(&scale[t + 5 * THREADS]);
        o5.x = v5.x * r4 * s.x;  o5.y = v5.y * r4 * s.y;
        o5.z = v5.z * r4 * s.z;  o5.w = v5.w * r4 * s.w;
    }
    {
        float4 s = __ldg(&scale[t + 6 * THREADS]);
        o6.x = v6.x * r4 * s.x;  o6.y = v6.y * r4 * s.y;
        o6.z = v6.z * r4 * s.z;  o6.w = v6.w * r4 * s.w;
    }
    {
        float4 s = __ldg(&scale[t + 7 * THREADS]);
        o7.x = v7.x * r4 * s.x;  o7.y = v7.y * r4 * s.y;
        o7.z = v7.z * r4 * s.z;  o7.w = v7.w * r4 * s.w;
    }

    __stcs(&orow[t],               o0);
    __stcs(&orow[t + 1 * THREADS], o1);
    __stcs(&orow[t + 2 * THREADS], o2);
    __stcs(&orow[t + 3 * THREADS], o3);
    __stcs(&orow[t + 4 * THREADS], o4);
    __stcs(&orow[t + 5 * THREADS], o5);
    __stcs(&orow[t + 6 * THREADS], o6);
    __stcs(&orow[t + 7 * THREADS], o7);
}

extern "C" void kernel_launch(void* const* d_in, const int* in_sizes, int n_in,
                              void* d_out, int out_size)
{
    const float4* x = (const float4*)d_in[0];
    const float4* scale = (const float4*)d_in[1];
    float4* out = (float4*)d_out;

    const int rows = out_size / D;   // 16384
    mrmsnorm_kernel<<<rows, THREADS>>>(x, scale, out);
}